// round 1
// baseline (speedup 1.0000x reference)
#include <cuda_runtime.h>
#include <math.h>

#define B_   4
#define HF_  64
#define WF_  64
#define CF_  256
#define CC_  256
#define F_   256
#define DG_  8
#define KK_  9
#define NPIX (B_*HF_*WF_)      /* 16384 */
#define OMC  216               /* 144 offsets + 72 masks */
#define KDCN 2304              /* KK*CC */

// ---------------- scratch (static device globals; no runtime alloc) --------
__device__ float g_part[32*B_*CF_];          // GAP partials
__device__ float g_scale[B_*CF_];            // attn+1
__device__ float g_fine_cal[NPIX*CF_];       // 16 MB
__device__ float g_coarse_up[NPIX*CC_];      // 16 MB
__device__ float g_align[NPIX*512];          // 32 MB
__device__ float g_om[NPIX*OMC];             // 14 MB

// ---------------- packed f32x2 helpers (Blackwell FFMA2) -------------------
static __device__ __forceinline__ unsigned long long f2pack(float lo, float hi){
    unsigned long long r;
    asm("mov.b64 %0, {%1,%2};" : "=l"(r) : "f"(lo), "f"(hi));
    return r;
}
static __device__ __forceinline__ unsigned long long ffma2(unsigned long long a,
                                                           unsigned long long b,
                                                           unsigned long long c){
    unsigned long long d;
    asm("fma.rn.f32x2 %0, %1, %2, %3;" : "=l"(d) : "l"(a), "l"(b), "l"(c));
    return d;
}
static __device__ __forceinline__ float2 f2unpack(unsigned long long v){
    float2 r;
    asm("mov.b64 {%0,%1}, %2;" : "=f"(r.x), "=f"(r.y) : "l"(v));
    return r;
}

// ---------------- 1) GAP partial sums ---------------------------------------
__global__ void gap_partial(const float* __restrict__ fine){
    int blk = blockIdx.x;            // b*32 + chunk
    int b = blk >> 5, chunk = blk & 31;
    int c = threadIdx.x;
    const float* p = fine + ((size_t)(b*4096 + chunk*128))*256 + c;
    float s = 0.f;
    #pragma unroll 8
    for (int r = 0; r < 128; r++) s += p[(size_t)r*256];
    g_part[blk*256 + c] = s;
}

// ---------------- 2) attention scale: sigmoid(gap @ W) + 1 ------------------
__global__ void attn_kernel(const float* __restrict__ W){
    __shared__ float gp[256];
    int b = blockIdx.x, t = threadIdx.x;
    float s = 0.f;
    #pragma unroll
    for (int ch = 0; ch < 32; ch++) s += g_part[(b*32 + ch)*256 + t];
    gp[t] = s * (1.f/4096.f);
    __syncthreads();
    float acc = 0.f;
    for (int c = 0; c < 256; c++) acc += gp[c] * W[c*256 + t];
    g_scale[b*256 + t] = 1.f + 1.f/(1.f + expf(-acc));
}

// ---------------- 3) coarse 2x bilinear upsample (half-pixel) ---------------
__global__ void upsample_kernel(const float* __restrict__ coarse){
    int m = blockIdx.x;
    int c = threadIdx.x;
    int b = m >> 12, rem = m & 4095;
    int y = rem >> 6, x = rem & 63;
    float fy = 0.5f*y - 0.25f, fx = 0.5f*x - 0.25f;
    float y0f = floorf(fy), x0f = floorf(fx);
    float wy1 = fy - y0f, wx1 = fx - x0f;
    float wy0 = 1.f - wy1, wx0 = 1.f - wx1;
    int y0 = (int)y0f, x0 = (int)x0f;
    int y0c = min(max(y0, 0), 31),  y1c = min(max(y0+1, 0), 31);
    int x0c = min(max(x0, 0), 31),  x1c = min(max(x0+1, 0), 31);
    const float* cb = coarse + (size_t)(b*1024)*256 + c;
    float v00 = cb[(y0c*32 + x0c)*256];
    float v01 = cb[(y0c*32 + x1c)*256];
    float v10 = cb[(y1c*32 + x0c)*256];
    float v11 = cb[(y1c*32 + x1c)*256];
    g_coarse_up[(size_t)m*256 + c] = wy0*(wx0*v00 + wx1*v01) + wy1*(wx0*v10 + wx1*v11);
}

// ---------------- tiled SGEMM (64x64x16, 4x4 microtile, FFMA2) --------------
// MODE 0: fine_cal = (fine * scale[b,k]) @ fs_conv_w         (K=256,N=256)
// MODE 1: align    = [fine_cal | 2*coarse_up] @ offset_w     (K=512,N=512)
// MODE 2: om       = implicit-im2col 3x3 conv(align) @ om_w  (K=4608,N=216)+b
template<int MODE>
__global__ __launch_bounds__(256)
void sgemm(const float* __restrict__ Aext,
           const float* __restrict__ Bw,
           const float* __restrict__ bias){
    constexpr int Kk = (MODE==0)?256:(MODE==1)?512:4608;
    constexpr int Nn = (MODE==0)?256:(MODE==1)?512:216;

    __shared__ __align__(16) float As[16][68];
    __shared__ __align__(16) float Bs[16][64];

    int tid = threadIdx.x;
    int tx = tid & 15, ty = tid >> 4;
    int m0 = blockIdx.x * 64, n0 = blockIdx.y * 64;

    int lm = tid >> 2;            // A row within tile
    int kq = (tid & 3) * 4;       // A k sub-offset (float4)
    int mrow = m0 + lm;
    int b   = mrow >> 12;
    int rem = mrow & 4095;
    int yy  = rem >> 6, xx = rem & 63;

    unsigned long long acc[4][2];
    #pragma unroll
    for (int i = 0; i < 4; i++){ acc[i][0] = 0ULL; acc[i][1] = 0ULL; }

    for (int k0 = 0; k0 < Kk; k0 += 16){
        // ---- A tile load (float4) ----
        float4 av;
        if (MODE == 0){
            float4 f4 = *(const float4*)(Aext + (size_t)mrow*256 + k0 + kq);
            float4 s4 = *(const float4*)(g_scale + b*256 + k0 + kq);
            av.x = f4.x*s4.x; av.y = f4.y*s4.y; av.z = f4.z*s4.z; av.w = f4.w*s4.w;
        } else if (MODE == 1){
            int kk = k0 + kq;
            if (kk < 256) av = *(const float4*)(g_fine_cal + (size_t)mrow*256 + kk);
            else {
                av = *(const float4*)(g_coarse_up + (size_t)mrow*256 + (kk - 256));
                av.x *= 2.f; av.y *= 2.f; av.z *= 2.f; av.w *= 2.f;
            }
        } else {
            int tap = k0 >> 9;                 // uniform within BK=16 chunk
            int c   = (k0 & 511) + kq;
            int ny  = yy + tap/3 - 1;
            int nx  = xx + tap%3 - 1;
            if (ny >= 0 && ny < 64 && nx >= 0 && nx < 64)
                av = *(const float4*)(g_align + (size_t)(((b<<12) + ny*64 + nx))*512 + c);
            else
                av = make_float4(0.f, 0.f, 0.f, 0.f);
        }
        As[kq+0][lm] = av.x; As[kq+1][lm] = av.y;
        As[kq+2][lm] = av.z; As[kq+3][lm] = av.w;

        // ---- B tile load (4 scalars) ----
        #pragma unroll
        for (int i = 0; i < 4; i++){
            int e  = tid + i*256;
            int kl = e >> 6, nl = e & 63;
            int n  = n0 + nl;
            float v = 0.f;
            if (MODE != 2 || n < 216) v = Bw[(size_t)(k0 + kl)*Nn + n];
            Bs[kl][nl] = v;
        }
        __syncthreads();

        #pragma unroll
        for (int kk = 0; kk < 16; kk++){
            float4 a4 = *(const float4*)&As[kk][ty*4];
            double2 bd = *(const double2*)&Bs[kk][tx*4];
            unsigned long long b01 = __double_as_longlong(bd.x);
            unsigned long long b23 = __double_as_longlong(bd.y);
            float aa[4] = {a4.x, a4.y, a4.z, a4.w};
            #pragma unroll
            for (int i = 0; i < 4; i++){
                unsigned long long ad = f2pack(aa[i], aa[i]);
                acc[i][0] = ffma2(ad, b01, acc[i][0]);
                acc[i][1] = ffma2(ad, b23, acc[i][1]);
            }
        }
        __syncthreads();
    }

    // ---- epilogue ----
    #pragma unroll
    for (int i = 0; i < 4; i++){
        int m = m0 + ty*4 + i;
        float2 c01 = f2unpack(acc[i][0]);
        float2 c23 = f2unpack(acc[i][1]);
        float v[4] = {c01.x, c01.y, c23.x, c23.y};
        #pragma unroll
        for (int j = 0; j < 4; j++){
            int n = n0 + tx*4 + j;
            if (MODE == 0)      g_fine_cal[(size_t)m*256 + n] = v[j];
            else if (MODE == 1) g_align[(size_t)m*512 + n]    = v[j];
            else if (n < 216)   g_om[(size_t)m*216 + n]       = v[j] + bias[n];
        }
    }
}

// ---------------- fused DCNv2: deform-sample + GEMM + ReLU + residual -------
__global__ __launch_bounds__(256, 1)
void dcn_fused(const float* __restrict__ dcnW,
               const float* __restrict__ dcnB,
               float* __restrict__ outp){
    extern __shared__ float sm[];
    float* cols = sm;                 // 16 * 2304
    float* oms  = sm + 16*KDCN;       // 16 * 216

    int tid = threadIdx.x;
    int pixBase = blockIdx.x * 16;

    // stage om rows (contiguous, coalesced)
    for (int i = tid; i < 16*OMC; i += 256)
        oms[i] = g_om[(size_t)pixBase*OMC + i];
    __syncthreads();

    // ---- phase 1: deformable sampling (1 warp -> 2 pixels) ----
    int warp = tid >> 5, lane = tid & 31;
    #pragma unroll
    for (int p2 = 0; p2 < 2; p2++){
        int pix = warp*2 + p2;
        int m = pixBase + pix;
        int b = m >> 12, rem = m & 4095;
        int y = rem >> 6, x = rem & 63;
        const float* om = oms + pix*OMC;
        for (int g = 0; g < 8; g++){
            int cbase = g*32 + lane;
            const float* base = g_coarse_up + (size_t)(b << 12)*256 + cbase;
            #pragma unroll
            for (int t = 0; t < 9; t++){
                float dy = om[g*18 + t*2];
                float dx = om[g*18 + t*2 + 1];
                float mk = 2.f / (1.f + expf(-om[144 + g*9 + t]));
                float py = (float)y + (float)(t/3 - 1) + dy;
                float px = (float)x + (float)(t%3 - 1) + dx;
                float y0f = floorf(py), x0f = floorf(px);
                float wy1 = py - y0f,  wx1 = px - x0f;
                float wy0 = 1.f - wy1, wx0 = 1.f - wx1;
                int y0 = (int)y0f, x0 = (int)x0f;
                bool yin0 = (y0 >= 0 && y0 < 64), yin1 = (y0+1 >= 0 && y0+1 < 64);
                bool xin0 = (x0 >= 0 && x0 < 64), xin1 = (x0+1 >= 0 && x0+1 < 64);
                float v00 = 0.f, v01 = 0.f, v10 = 0.f, v11 = 0.f;
                if (yin0 && xin0) v00 = base[(size_t)(y0*64 + x0    )*256];
                if (yin0 && xin1) v01 = base[(size_t)(y0*64 + x0 + 1)*256];
                if (yin1 && xin0) v10 = base[(size_t)((y0+1)*64 + x0    )*256];
                if (yin1 && xin1) v11 = base[(size_t)((y0+1)*64 + x0 + 1)*256];
                float val = mk * (v00*(wy0*wx0) + v01*(wy0*wx1)
                                + v10*(wy1*wx0) + v11*(wy1*wx1));
                cols[pix*KDCN + t*256 + cbase] = val;
            }
        }
    }
    __syncthreads();

    // ---- phase 2: [16 x 2304] x [2304 x 256] with FFMA2 over k-pairs ----
    int f = tid;
    unsigned long long acc[16];
    #pragma unroll
    for (int p = 0; p < 16; p++) acc[p] = 0ULL;

    #pragma unroll 1
    for (int k = 0; k < KDCN; k += 4){
        float w0 = dcnW[(size_t)(k+0)*256 + f];
        float w1 = dcnW[(size_t)(k+1)*256 + f];
        float w2 = dcnW[(size_t)(k+2)*256 + f];
        float w3 = dcnW[(size_t)(k+3)*256 + f];
        unsigned long long w01 = f2pack(w0, w1);
        unsigned long long w23 = f2pack(w2, w3);
        #pragma unroll
        for (int p = 0; p < 16; p++){
            double2 cd = *(const double2*)(cols + p*KDCN + k);
            acc[p] = ffma2(__double_as_longlong(cd.x), w01, acc[p]);
            acc[p] = ffma2(__double_as_longlong(cd.y), w23, acc[p]);
        }
    }
    float bia = dcnB[f];
    #pragma unroll
    for (int p = 0; p < 16; p++){
        float2 s = f2unpack(acc[p]);
        float v = s.x + s.y + bia;
        v = fmaxf(v, 0.f);
        int m = pixBase + p;
        outp[(size_t)m*256 + f] = v + g_fine_cal[(size_t)m*256 + f];
    }
}

// ---------------- launcher ---------------------------------------------------
extern "C" void kernel_launch(void* const* d_in, const int* in_sizes, int n_in,
                              void* d_out, int out_size){
    const float* fine      = (const float*)d_in[0];
    const float* coarse    = (const float*)d_in[1];
    const float* fs_attn_w = (const float*)d_in[2];
    const float* fs_conv_w = (const float*)d_in[3];
    const float* offset_w  = (const float*)d_in[4];
    const float* om_w      = (const float*)d_in[5];
    const float* om_b      = (const float*)d_in[6];
    const float* dcn_w     = (const float*)d_in[7];
    const float* dcn_b     = (const float*)d_in[8];
    float* out = (float*)d_out;

    (void)in_sizes; (void)n_in; (void)out_size;

    const int dcn_smem = (16*KDCN + 16*OMC) * (int)sizeof(float);  // 161280 B
    cudaFuncSetAttribute(dcn_fused, cudaFuncAttributeMaxDynamicSharedMemorySize, dcn_smem);

    gap_partial  <<<128,   256>>>(fine);
    attn_kernel  <<<4,     256>>>(fs_attn_w);
    upsample_kernel<<<NPIX, 256>>>(coarse);
    sgemm<0>     <<<dim3(256, 4), 256>>>(fine,    fs_conv_w, nullptr);
    sgemm<1>     <<<dim3(256, 8), 256>>>(nullptr, offset_w,  nullptr);
    sgemm<2>     <<<dim3(256, 4), 256>>>(nullptr, om_w,      om_b);
    dcn_fused    <<<1024, 256, dcn_smem>>>(dcn_w, dcn_b, out);
}

// round 3
// speedup vs baseline: 3.5823x; 3.5823x over previous
#include <cuda_runtime.h>
#include <cuda_fp16.h>
#include <math.h>
#include <stdint.h>

#define B_   4
#define NPIX 16384
#define OMC  216
#define KDCN 2304

// ---------------- scratch (device globals; zero-init at load) ---------------
__device__ float g_part[32*B_*256];
__device__ float g_scale[B_*256];
__device__ float g_fine_cal[NPIX*256];
__device__ float g_coarse_up[NPIX*256];
__device__ float g_om[NPIX*OMC];

__device__ __half g_fs_hi[NPIX*256],  g_fs_lo[NPIX*256];
__device__ __half g_cat_hi[NPIX*512], g_cat_lo[NPIX*512];
__device__ __half g_cols_hi[(size_t)NPIX*KDCN], g_cols_lo[(size_t)NPIX*KDCN];

// transposed split weights Bt[n][k]
__device__ __half g_bt0h[256*256],  g_bt0l[256*256];    // fs_conv_w
__device__ __half g_bt2h[256*4608], g_bt2l[256*4608];   // Wcomb (pad n 216->256, zero)
__device__ __half g_bt3h[256*2304], g_bt3l[256*2304];   // dcn_kernel

// ---------------- helpers ----------------------------------------------------
static __device__ __forceinline__ uint32_t smem_u32(const void* p){
    uint32_t a;
    asm("{ .reg .u64 t; cvta.to.shared.u64 t, %1; cvt.u32.u64 %0, t; }" : "=r"(a) : "l"(p));
    return a;
}
static __device__ __forceinline__ void cpa16(uint32_t dst, const void* src, int pbytes){
    asm volatile("cp.async.ca.shared.global [%0], [%1], 16, %2;"
                 :: "r"(dst), "l"(src), "r"(pbytes));
}
#define CP_COMMIT  asm volatile("cp.async.commit_group;" ::: "memory")
#define CP_WAIT1   asm volatile("cp.async.wait_group 1;" ::: "memory")
#define CP_WAIT0   asm volatile("cp.async.wait_group 0;" ::: "memory")
#define LDSM_X4(r, a) \
    asm volatile("ldmatrix.sync.aligned.m8n8.x4.shared.b16 {%0,%1,%2,%3}, [%4];" \
        : "=r"((r)[0]),"=r"((r)[1]),"=r"((r)[2]),"=r"((r)[3]) : "r"(a))
#define MMA16816(d, a, b0, b1) \
    asm volatile("mma.sync.aligned.m16n8k16.row.col.f32.f16.f16.f32 " \
        "{%0,%1,%2,%3}, {%4,%5,%6,%7}, {%8,%9}, {%0,%1,%2,%3};" \
        : "+f"((d)[0]),"+f"((d)[1]),"+f"((d)[2]),"+f"((d)[3]) \
        : "r"((a)[0]),"r"((a)[1]),"r"((a)[2]),"r"((a)[3]), "r"(b0), "r"(b1))

static __device__ __forceinline__ void split2(float v, __half& h, __half& l){
    h = __float2half_rn(v);
    l = __float2half_rn(v - __half2float(h));
}
static __device__ __forceinline__ uint32_t packsplit(float x, float y, uint32_t& lo){
    __half hx, lx, hy, ly;
    split2(x, hx, lx); split2(y, hy, ly);
    lo = (uint32_t)__half_as_ushort(lx) | ((uint32_t)__half_as_ushort(ly) << 16);
    return (uint32_t)__half_as_ushort(hx) | ((uint32_t)__half_as_ushort(hy) << 16);
}
// packed f32x2 for the fp32 Wcomb GEMM
static __device__ __forceinline__ unsigned long long f2pack(float lo, float hi){
    unsigned long long r;
    asm("mov.b64 %0, {%1,%2};" : "=l"(r) : "f"(lo), "f"(hi));
    return r;
}
static __device__ __forceinline__ unsigned long long ffma2(unsigned long long a,
                                                           unsigned long long b,
                                                           unsigned long long c){
    unsigned long long d;
    asm("fma.rn.f32x2 %0, %1, %2, %3;" : "=l"(d) : "l"(a), "l"(b), "l"(c));
    return d;
}
static __device__ __forceinline__ float2 f2unpack(unsigned long long v){
    float2 r;
    asm("mov.b64 {%0,%1}, %2;" : "=f"(r.x), "=f"(r.y) : "l"(v));
    return r;
}

// ---------------- prep kernels ------------------------------------------------
__global__ void gap_partial(const float* __restrict__ fine){
    int blk = blockIdx.x, b = blk >> 5, chunk = blk & 31, c = threadIdx.x;
    const float* p = fine + ((size_t)(b*4096 + chunk*128))*256 + c;
    float s = 0.f;
    #pragma unroll 8
    for (int r = 0; r < 128; r++) s += p[(size_t)r*256];
    g_part[blk*256 + c] = s;
}
__global__ void attn_kernel(const float* __restrict__ W){
    __shared__ float gp[256];
    int b = blockIdx.x, t = threadIdx.x;
    float s = 0.f;
    #pragma unroll
    for (int ch = 0; ch < 32; ch++) s += g_part[(b*32 + ch)*256 + t];
    gp[t] = s * (1.f/4096.f);
    __syncthreads();
    float acc = 0.f;
    for (int c = 0; c < 256; c++) acc += gp[c] * W[c*256 + t];
    g_scale[b*256 + t] = 1.f + 1.f/(1.f + expf(-acc));
}
__global__ void upsample_kernel(const float* __restrict__ coarse){
    int m = blockIdx.x, c = threadIdx.x;
    int b = m >> 12, rem = m & 4095, y = rem >> 6, x = rem & 63;
    float fy = 0.5f*y - 0.25f, fx = 0.5f*x - 0.25f;
    float y0f = floorf(fy), x0f = floorf(fx);
    float wy1 = fy - y0f, wx1 = fx - x0f, wy0 = 1.f - wy1, wx0 = 1.f - wx1;
    int y0 = (int)y0f, x0 = (int)x0f;
    int y0c = min(max(y0,0),31), y1c = min(max(y0+1,0),31);
    int x0c = min(max(x0,0),31), x1c = min(max(x0+1,0),31);
    const float* cb = coarse + (size_t)(b*1024)*256 + c;
    float v = wy0*(wx0*cb[(y0c*32+x0c)*256] + wx1*cb[(y0c*32+x1c)*256])
            + wy1*(wx0*cb[(y1c*32+x0c)*256] + wx1*cb[(y1c*32+x1c)*256]);
    g_coarse_up[(size_t)m*256 + c] = v;
    __half h, l; split2(2.f*v, h, l);
    g_cat_hi[(size_t)m*512 + 256 + c] = h;
    g_cat_lo[(size_t)m*512 + 256 + c] = l;
}
__global__ void fsplit(const float* __restrict__ fine){
    int m = blockIdx.x, c = threadIdx.x, b = m >> 12;
    float v = fine[(size_t)m*256 + c] * g_scale[b*256 + c];
    __half h, l; split2(v, h, l);
    g_fs_hi[(size_t)m*256 + c] = h;
    g_fs_lo[(size_t)m*256 + c] = l;
}
// transpose + split weights: W[k][n] -> Bt[n][k]   (WI=0: fs_conv, WI=3: dcn)
template<int WI>
__global__ void wsplit(const float* __restrict__ W){
    constexpr int K  = (WI==0) ? 256 : 2304;
    __half* bh = (WI==0) ? g_bt0h : g_bt3h;
    __half* bl = (WI==0) ? g_bt0l : g_bt3l;
    int k = blockIdx.x*256 + threadIdx.x;
    int n = blockIdx.y;
    if (k >= K) return;
    float v = W[(size_t)k*256 + n];
    __half h, l; split2(v, h, l);
    bh[(size_t)n*K + k] = h;
    bl[(size_t)n*K + k] = l;
}

// ---- Wcomb: per tap, C[c][n] = offset_w[c][:] . om_w[tap][:][n]  (fp32 FFMA2)
__global__ __launch_bounds__(256)
void wcomb(const float* __restrict__ offw, const float* __restrict__ omw){
    __shared__ __align__(16) float As[16][68];
    __shared__ __align__(16) float Bs[16][64];
    int tid = threadIdx.x, tx = tid & 15, ty = tid >> 4;
    int m0 = blockIdx.x*64, n0 = blockIdx.y*64, tap = blockIdx.z;
    const float* Bw = omw + (size_t)tap*512*216;
    int lm = tid >> 2, kq = (tid & 3)*4;
    int mrow = m0 + lm;
    unsigned long long acc[4][2];
    #pragma unroll
    for (int i = 0; i < 4; i++){ acc[i][0] = 0ULL; acc[i][1] = 0ULL; }
    for (int k0 = 0; k0 < 512; k0 += 16){
        float4 av = *(const float4*)(offw + (size_t)mrow*512 + k0 + kq);
        As[kq+0][lm] = av.x; As[kq+1][lm] = av.y;
        As[kq+2][lm] = av.z; As[kq+3][lm] = av.w;
        #pragma unroll
        for (int i = 0; i < 4; i++){
            int e = tid + i*256, kl = e >> 6, nl = e & 63, n = n0 + nl;
            Bs[kl][nl] = (n < 216) ? Bw[(size_t)(k0 + kl)*216 + n] : 0.f;
        }
        __syncthreads();
        #pragma unroll
        for (int kk = 0; kk < 16; kk++){
            float4 a4 = *(const float4*)&As[kk][ty*4];
            double2 bd = *(const double2*)&Bs[kk][tx*4];
            unsigned long long b01 = __double_as_longlong(bd.x);
            unsigned long long b23 = __double_as_longlong(bd.y);
            float aa[4] = {a4.x, a4.y, a4.z, a4.w};
            #pragma unroll
            for (int i = 0; i < 4; i++){
                unsigned long long ad = f2pack(aa[i], aa[i]);
                acc[i][0] = ffma2(ad, b01, acc[i][0]);
                acc[i][1] = ffma2(ad, b23, acc[i][1]);
            }
        }
        __syncthreads();
    }
    #pragma unroll
    for (int i = 0; i < 4; i++){
        int m = m0 + ty*4 + i;
        float2 c01 = f2unpack(acc[i][0]), c23 = f2unpack(acc[i][1]);
        float v[4] = {c01.x, c01.y, c23.x, c23.y};
        #pragma unroll
        for (int j = 0; j < 4; j++){
            int n = n0 + tx*4 + j;
            if (n < 216){
                __half h, l; split2(v[j], h, l);
                g_bt2h[(size_t)n*4608 + tap*512 + m] = h;
                g_bt2l[(size_t)n*4608 + tap*512 + m] = l;
            }
        }
    }
}

// ---------------- warp-MMA split-fp16 GEMM (BM128 BN128 BK64, cp.async db) ---
// MODE 0: fine_cal = fs @ bt0          (K=256)
// MODE 2: om = im2col(cat) @ bt2 + b   (K=4608, n<216)
// MODE 3: out = relu(cols @ bt3 + b) + fine_cal  (K=2304)
template<int MODE>
__global__ void __launch_bounds__(256)
mmagemm(const float* __restrict__ bias, float* __restrict__ outp){
    constexpr int Kk = (MODE==0) ? 256 : (MODE==2) ? 4608 : 2304;
    constexpr int NC = Kk / 64;
    const __half* Ah = (MODE==0) ? g_fs_hi : (MODE==2) ? g_cat_hi : g_cols_hi;
    const __half* Al = (MODE==0) ? g_fs_lo : (MODE==2) ? g_cat_lo : g_cols_lo;
    const __half* Bh = (MODE==0) ? g_bt0h : (MODE==2) ? g_bt2h : g_bt3h;
    const __half* Bl = (MODE==0) ? g_bt0l : (MODE==2) ? g_bt2l : g_bt3l;

    extern __shared__ __align__(16) char smem[];
    uint32_t sb = smem_u32(smem);
    int tid = threadIdx.x, lane = tid & 31, wid = tid >> 5;
    int m0 = blockIdx.x*128, n0 = blockIdx.y*128;
    int wm = wid >> 2, wn = wid & 3;

    auto load_chunk = [&](int stage, int k0){
        uint32_t base = sb + stage*65536;
        #pragma unroll
        for (int u = 0; u < 4; u++){
            int idx = tid + u*256;
            int row = idx >> 3, ch = idx & 7;
            uint32_t d = base + (uint32_t)(row*128 + ((ch ^ (row & 7)) << 4));
            size_t boff = (size_t)(n0 + row)*Kk + k0 + ch*8;
            cpa16(d + 32768, Bh + boff, 16);
            cpa16(d + 49152, Bl + boff, 16);
            if (MODE == 2){
                int m = m0 + row, bb = m >> 12, rem = m & 4095;
                int yy = rem >> 6, xx = rem & 63;
                int tap = k0 >> 9, cc = (k0 & 511) + ch*8;
                int ny = yy + tap/3 - 1, nx = xx + tap%3 - 1;
                bool ok = ((unsigned)ny < 64u) && ((unsigned)nx < 64u);
                size_t aoff = ok ? ((size_t)((bb << 12) + ny*64 + nx)*512 + cc) : 0;
                int pb = ok ? 16 : 0;
                cpa16(d,         Ah + aoff, pb);
                cpa16(d + 16384, Al + aoff, pb);
            } else {
                size_t aoff = (size_t)(m0 + row)*Kk + k0 + ch*8;
                cpa16(d,         Ah + aoff, 16);
                cpa16(d + 16384, Al + aoff, 16);
            }
        }
    };

    int rbase = wm*64 + ((lane >> 3) & 1)*8 + (lane & 7);
    int khA   = lane >> 4;
    int nbase = wn*32 + ((lane >> 4) & 1)*8 + (lane & 7);
    int khB   = (lane >> 3) & 1;
    uint32_t aswz = (uint32_t)(rbase & 7), bswz = (uint32_t)(nbase & 7);

    float acc[4][4][4];
    #pragma unroll
    for (int i = 0; i < 4; i++)
        #pragma unroll
        for (int j = 0; j < 4; j++)
            #pragma unroll
            for (int q = 0; q < 4; q++) acc[i][j][q] = 0.f;

    load_chunk(0, 0);
    CP_COMMIT;
    for (int c = 0; c < NC; c++){
        if (c + 1 < NC) load_chunk((c + 1) & 1, (c + 1)*64);
        CP_COMMIT;
        if (c + 1 < NC) CP_WAIT1; else CP_WAIT0;
        __syncthreads();
        uint32_t base = sb + (c & 1)*65536;
        #pragma unroll
        for (int ks = 0; ks < 4; ks++){
            uint32_t aH[4][4], aL[4][4], bH[2][4], bL[2][4];
            #pragma unroll
            for (int mi = 0; mi < 4; mi++){
                uint32_t off = base + (uint32_t)((rbase + mi*16)*128
                             + ((((uint32_t)(ks*2 + khA)) ^ aswz) << 4));
                LDSM_X4(aH[mi], off);
                LDSM_X4(aL[mi], off + 16384);
            }
            #pragma unroll
            for (int nb = 0; nb < 2; nb++){
                uint32_t off = base + 32768 + (uint32_t)((nbase + nb*16)*128
                             + ((((uint32_t)(ks*2 + khB)) ^ bswz) << 4));
                LDSM_X4(bH[nb], off);
                LDSM_X4(bL[nb], off + 16384);
            }
            #pragma unroll
            for (int mi = 0; mi < 4; mi++)
                #pragma unroll
                for (int nj = 0; nj < 4; nj++){
                    uint32_t h0 = bH[nj >> 1][(nj & 1)*2], h1 = bH[nj >> 1][(nj & 1)*2 + 1];
                    uint32_t l0 = bL[nj >> 1][(nj & 1)*2], l1 = bL[nj >> 1][(nj & 1)*2 + 1];
                    MMA16816(acc[mi][nj], aH[mi], h0, h1);
                    MMA16816(acc[mi][nj], aH[mi], l0, l1);
                    MMA16816(acc[mi][nj], aL[mi], h0, h1);
                }
        }
        __syncthreads();
    }

    // ---- epilogue ----
    int g = lane >> 2, th = lane & 3;
    #pragma unroll
    for (int mi = 0; mi < 4; mi++){
        #pragma unroll
        for (int nj = 0; nj < 4; nj++){
            int col = n0 + wn*32 + nj*8 + th*2;
            float* a = acc[mi][nj];
            #pragma unroll
            for (int half = 0; half < 2; half++){
                int m = m0 + wm*64 + mi*16 + g + half*8;
                float x = a[half*2], y = a[half*2 + 1];
                if (MODE == 0){
                    *(float2*)(g_fine_cal + (size_t)m*256 + col) = make_float2(x, y);
                    uint32_t lo, hi = packsplit(x, y, lo);
                    *(uint32_t*)(g_cat_hi + (size_t)m*512 + col) = hi;
                    *(uint32_t*)(g_cat_lo + (size_t)m*512 + col) = lo;
                } else if (MODE == 2){
                    if (col < OMC)
                        *(float2*)(g_om + (size_t)m*OMC + col) =
                            make_float2(x + bias[col], y + bias[col + 1]);
                } else {
                    float2 fc = *(const float2*)(g_fine_cal + (size_t)m*256 + col);
                    float2 o;
                    o.x = fmaxf(x + bias[col],     0.f) + fc.x;
                    o.y = fmaxf(y + bias[col + 1], 0.f) + fc.y;
                    *(float2*)(outp + (size_t)m*256 + col) = o;
                }
            }
        }
    }
}

// ---------------- deformable sampling -> split fp16 columns ------------------
__global__ __launch_bounds__(256)
void dcn_sample(){
    __shared__ float oms[16*OMC];
    int tid = threadIdx.x;
    int pixBase = blockIdx.x * 16;
    for (int i = tid; i < 16*OMC; i += 256)
        oms[i] = g_om[(size_t)pixBase*OMC + i];
    __syncthreads();

    int warp = tid >> 5, lane = tid & 31;
    #pragma unroll
    for (int p2 = 0; p2 < 2; p2++){
        int pix = warp*2 + p2;
        int m = pixBase + pix;
        int b = m >> 12, rem = m & 4095, y = rem >> 6, x = rem & 63;
        const float* om = oms + pix*OMC;
        for (int g = 0; g < 8; g++){
            int cbase = g*32 + lane;
            const float* base = g_coarse_up + (size_t)(b << 12)*256 + cbase;
            #pragma unroll
            for (int t = 0; t < 9; t++){
                float dy = om[g*18 + t*2];
                float dx = om[g*18 + t*2 + 1];
                float mk = 2.f / (1.f + expf(-om[144 + g*9 + t]));
                float py = (float)y + (float)(t/3 - 1) + dy;
                float px = (float)x + (float)(t%3 - 1) + dx;
                float y0f = floorf(py), x0f = floorf(px);
                float wy1 = py - y0f, wx1 = px - x0f;
                float wy0 = 1.f - wy1, wx0 = 1.f - wx1;
                int y0 = (int)y0f, x0 = (int)x0f;
                bool yin0 = (y0 >= 0 && y0 < 64), yin1 = (y0+1 >= 0 && y0+1 < 64);
                bool xin0 = (x0 >= 0 && x0 < 64), xin1 = (x0+1 >= 0 && x0+1 < 64);
                float v00 = 0.f, v01 = 0.f, v10 = 0.f, v11 = 0.f;
                if (yin0 && xin0) v00 = base[(size_t)(y0*64 + x0    )*256];
                if (yin0 && xin1) v01 = base[(size_t)(y0*64 + x0 + 1)*256];
                if (yin1 && xin0) v10 = base[(size_t)((y0+1)*64 + x0    )*256];
                if (yin1 && xin1) v11 = base[(size_t)((y0+1)*64 + x0 + 1)*256];
                float val = mk * (v00*(wy0*wx0) + v01*(wy0*wx1)
                                + v10*(wy1*wx0) + v11*(wy1*wx1));
                __half h, l; split2(val, h, l);
                size_t idx = (size_t)m*KDCN + t*256 + cbase;
                g_cols_hi[idx] = h;
                g_cols_lo[idx] = l;
            }
        }
    }
}

// ---------------- launcher ----------------------------------------------------
extern "C" void kernel_launch(void* const* d_in, const int* in_sizes, int n_in,
                              void* d_out, int out_size){
    const float* fine      = (const float*)d_in[0];
    const float* coarse    = (const float*)d_in[1];
    const float* fs_attn_w = (const float*)d_in[2];
    const float* fs_conv_w = (const float*)d_in[3];
    const float* offset_w  = (const float*)d_in[4];
    const float* om_w      = (const float*)d_in[5];
    const float* om_b      = (const float*)d_in[6];
    const float* dcn_w     = (const float*)d_in[7];
    const float* dcn_b     = (const float*)d_in[8];
    float* out = (float*)d_out;
    (void)in_sizes; (void)n_in; (void)out_size;

    const int GSM = 131072;   // 2 stages x (AH,AL,BH,BL) x 16KB
    cudaFuncSetAttribute(mmagemm<0>, cudaFuncAttributeMaxDynamicSharedMemorySize, GSM);
    cudaFuncSetAttribute(mmagemm<2>, cudaFuncAttributeMaxDynamicSharedMemorySize, GSM);
    cudaFuncSetAttribute(mmagemm<3>, cudaFuncAttributeMaxDynamicSharedMemorySize, GSM);

    gap_partial     <<<128,   256>>>(fine);
    attn_kernel     <<<4,     256>>>(fs_attn_w);
    upsample_kernel <<<NPIX,  256>>>(coarse);
    fsplit          <<<NPIX,  256>>>(fine);
    wsplit<0>       <<<dim3(1, 256), 256>>>(fs_conv_w);
    wsplit<3>       <<<dim3(9, 256), 256>>>(dcn_w);
    wcomb           <<<dim3(8, 4, 9), 256>>>(offset_w, om_w);

    mmagemm<0> <<<dim3(128, 2), 256, GSM>>>(nullptr, nullptr);
    mmagemm<2> <<<dim3(128, 2), 256, GSM>>>(om_b,   nullptr);
    dcn_sample <<<1024, 256>>>();
    mmagemm<3> <<<dim3(128, 2), 256, GSM>>>(dcn_b,  out);
}